// round 11
// baseline (speedup 1.0000x reference)
#include <cuda_runtime.h>
#include <cuda_bf16.h>
#include <cuda_fp16.h>
#include <cstdint>
#include <cstddef>

// Problem shape (fixed by reference): B=16, T=1024, D=256
#define BB 16
#define TT 1024
#define DD 256

#define TILE 128
#define KC   64        // K chunk staged through smem (4 chunks)
#define STRIDE 72      // bf16 units per smem row (64+8 pad): conflict-free ldsm, 16B-aligned
#define WSTR 136       // fp16 units per w-smem row (128+8 pad)

#define C_YX 61.72839506172839f   // 1/(2*0.09^2)
#define C_HW 5.555555555555555f   // 1/(2*0.3^2)

// dynamic smem layout (bytes)
#define BUFB  (TILE * STRIDE * 2)     // 18432 per buffer
#define SM_A   0                      // 2 bufs: 36864
#define SM_B   36864                  // 2 bufs: 36864 -> 73728
#define SM_W   73728                  // 128 x 136 fp16 = 34816 -> 108544
#define SM_RED 108544                 // 32 floats
#define SMEM_TOTAL 108672

__device__ float g_num[BB];
__device__ float g_den[BB];
__device__ __nv_bfloat16 g_zb[BB * TT * DD];   // bf16 copy of z (8.4 MB scratch)

__device__ __forceinline__ uint32_t smem_u32(const void* p) {
    return (uint32_t)__cvta_generic_to_shared(p);
}
__device__ __forceinline__ void cp16(uint32_t dst, const void* src) {
    asm volatile("cp.async.cg.shared.global [%0], [%1], 16;\n" :: "r"(dst), "l"(src));
}
__device__ __forceinline__ void mma_bf16(float c[4], const uint32_t a[4], const uint32_t b0,
                                         const uint32_t b1) {
    asm volatile(
        "mma.sync.aligned.m16n8k16.row.col.f32.bf16.bf16.f32 "
        "{%0,%1,%2,%3}, {%4,%5,%6,%7}, {%8,%9}, {%0,%1,%2,%3};"
        : "+f"(c[0]), "+f"(c[1]), "+f"(c[2]), "+f"(c[3])
        : "r"(a[0]), "r"(a[1]), "r"(a[2]), "r"(a[3]), "r"(b0), "r"(b1));
}
__device__ __forceinline__ void ldsm_x4(uint32_t r[4], uint32_t a) {
    asm volatile("ldmatrix.sync.aligned.m8n8.x4.shared.b16 {%0,%1,%2,%3}, [%4];"
        : "=r"(r[0]), "=r"(r[1]), "=r"(r[2]), "=r"(r[3]) : "r"(a));
}

// ---------------------------------------------------------------------------
// Prep: z (fp32) -> g_zb (bf16); zero accumulators. 512 x 256, 8 f4/thread.
// ---------------------------------------------------------------------------
__global__ void prep_kernel(const float4* __restrict__ z4) {
    if (blockIdx.x == 0 && threadIdx.x < BB) {
        g_num[threadIdx.x] = 0.0f;
        g_den[threadIdx.x] = 0.0f;
    }
    int base = blockIdx.x * 2048 + threadIdx.x;
    float4 v[8];
#pragma unroll
    for (int i = 0; i < 8; i++) v[i] = z4[base + i * 256];
#pragma unroll
    for (int i = 0; i < 8; i++) {
        __nv_bfloat162 lo = __floats2bfloat162_rn(v[i].x, v[i].y);
        __nv_bfloat162 hi = __floats2bfloat162_rn(v[i].z, v[i].w);
        uint2 pk;
        pk.x = *(uint32_t*)&lo;
        pk.y = *(uint32_t*)&hi;
        *(uint2*)(g_zb + (size_t)(base + i * 256) * 4) = pk;
    }
}

// ---------------------------------------------------------------------------
// Fused, interleaved: every warp both computes its 32x32 G sub-tile (bf16
// mma.sync, cp.async double-buffered K-chunks) AND streams 2 dT rows per
// chunk iteration (front-batched LDG.128 -> exp -> fp16 smem w-tile).
// DRAM streaming overlaps the entire GEMM. After the mainloop: combine
// Sum(w*G) from fragments vs smem w.  num = 2*Sum(w) - 2*Sum(w*G) (z2==1).
// grid = (8,8,16), block = 512 (16 warps, 4x4 warp grid).
// ---------------------------------------------------------------------------
__global__ __launch_bounds__(512, 1)
void fused_kernel(const float4* __restrict__ dT4) {
    extern __shared__ char sm[];
    const uint32_t smb = smem_u32(sm);
    __half* smW = (__half*)(sm + SM_W);
    float*  red = (float*)(sm + SM_RED);

    const int b  = blockIdx.z;
    const int t0 = blockIdx.y * TILE;
    const int s0 = blockIdx.x * TILE;

    const int tid  = threadIdx.x;
    const int warp = tid >> 5;
    const int lane = tid & 31;
    const int wr   = warp & 3;    // row quarter (32 rows)
    const int wc   = warp >> 2;   // col quarter (32 cols)
    const int g    = lane >> 2;
    const int tg   = lane & 3;

    const __nv_bfloat16* zbA = g_zb + (size_t)b * TT * DD + (size_t)t0 * DD;
    const __nv_bfloat16* zbB = g_zb + (size_t)b * TT * DD + (size_t)s0 * DD;

    // staging coords: 1024 16B-units per 128x64 tile; 2 units per thread/tile
    const int r0 = tid >> 3, c0 = (tid & 7);
    const int r1 = (tid + 512) >> 3, c1 = ((tid + 512) & 7);

    // ldsm byte offsets within a buffer
    uint32_t offA[2], offB[2];
    {
        const int rowA = lane & 15;
        const int colA = (lane >> 4) << 3;
#pragma unroll
        for (int mi = 0; mi < 2; mi++)
            offA[mi] = ((wr * 32 + mi * 16 + rowA) * STRIDE + colA) * 2;
        // B x4: matrices (lane>>3) = {ni even k0, ni even k8, ni odd k0, ni odd k8}
        const int rowB = ((lane >> 4) << 3) + (lane & 7);
        const int colB = ((lane >> 3) & 1) << 3;
#pragma unroll
        for (int np = 0; np < 2; np++)
            offB[np] = ((wc * 32 + np * 16 + rowB) * STRIDE + colB) * 2;
    }

    float acc[2][4][4];
#pragma unroll
    for (int mi = 0; mi < 2; mi++)
#pragma unroll
        for (int ni = 0; ni < 4; ni++)
#pragma unroll
            for (int j = 0; j < 4; j++) acc[mi][ni][j] = 0.0f;

    // ---- prologue: stage chunk 0 into buffer 0 ----
    cp16(smb + SM_A + r0 * (STRIDE * 2) + c0 * 16, zbA + (size_t)r0 * DD + c0 * 8);
    cp16(smb + SM_B + r0 * (STRIDE * 2) + c0 * 16, zbB + (size_t)r0 * DD + c0 * 8);
    cp16(smb + SM_A + r1 * (STRIDE * 2) + c1 * 16, zbA + (size_t)r1 * DD + c1 * 8);
    cp16(smb + SM_B + r1 * (STRIDE * 2) + c1 * 16, zbB + (size_t)r1 * DD + c1 * 8);
    asm volatile("cp.async.commit_group;\n" ::);

    const size_t dbase = (size_t)b * TT * TT + (size_t)t0 * TT + s0;
    float sum_w = 0.0f;

#pragma unroll
    for (int kci = 0; kci < DD / KC; kci++) {
        // 1) stage next chunk (other buffer)
        if (kci < DD / KC - 1) {
            const int kn = (kci + 1) * KC;
            const uint32_t bA = smb + SM_A + ((kci + 1) & 1) * BUFB;
            const uint32_t bB = smb + SM_B + ((kci + 1) & 1) * BUFB;
            cp16(bA + r0 * (STRIDE * 2) + c0 * 16, zbA + (size_t)r0 * DD + kn + c0 * 8);
            cp16(bB + r0 * (STRIDE * 2) + c0 * 16, zbB + (size_t)r0 * DD + kn + c0 * 8);
            cp16(bA + r1 * (STRIDE * 2) + c1 * 16, zbA + (size_t)r1 * DD + kn + c1 * 8);
            cp16(bB + r1 * (STRIDE * 2) + c1 * 16, zbB + (size_t)r1 * DD + kn + c1 * 8);
            asm volatile("cp.async.commit_group;\n" ::);
        }

        // 2) front-batch this iteration's dT stream: 2 rows per warp
        const int row = kci * 32 + warp * 2;
        const float4* p = dT4 + dbase + (size_t)row * TT;
        float4 d[2][4];
#pragma unroll
        for (int rr = 0; rr < 2; rr++)
#pragma unroll
            for (int it = 0; it < 4; it++)
                d[rr][it] = __ldg(p + (size_t)rr * TT + it * 32 + lane);

        // 3) wait staged chunk, barrier
        if (kci < DD / KC - 1)
            asm volatile("cp.async.wait_group 1;\n" ::);
        else
            asm volatile("cp.async.wait_group 0;\n" ::);
        __syncthreads();

        // 4) GEMM on current buffer (dT loads still in flight)
        const uint32_t bufA = smb + SM_A + (kci & 1) * BUFB;
        const uint32_t bufB = smb + SM_B + (kci & 1) * BUFB;
#pragma unroll
        for (int k0 = 0; k0 < KC; k0 += 16) {
            uint32_t af[2][4], bq[2][4];
#pragma unroll
            for (int mi = 0; mi < 2; mi++) ldsm_x4(af[mi], bufA + offA[mi] + k0 * 2);
#pragma unroll
            for (int np = 0; np < 2; np++) ldsm_x4(bq[np], bufB + offB[np] + k0 * 2);
#pragma unroll
            for (int mi = 0; mi < 2; mi++) {
#pragma unroll
                for (int np = 0; np < 2; np++) {
                    mma_bf16(acc[mi][np * 2],     af[mi], bq[np][0], bq[np][1]);
                    mma_bf16(acc[mi][np * 2 + 1], af[mi], bq[np][2], bq[np][3]);
                }
            }
        }

        // 5) consume streamed rows: w = exp(-e) -> smem + Sum w
#pragma unroll
        for (int rr = 0; rr < 2; rr++) {
            __half* wp = smW + (row + rr) * WSTR;
#pragma unroll
            for (int it = 0; it < 4; it++) {
                float4 q = d[rr][it];
                float e = (q.x * q.x + q.y * q.y) * C_YX
                        + (q.z * q.z + q.w * q.w) * C_HW;
                float w = __expf(-e);
                sum_w += w;
                wp[it * 32 + lane] = __float2half_rn(w);
            }
        }

        // 6) all reads of current buffer done before it is restaged next iter
        __syncthreads();
    }

    // ---- combine: Sum(w * G) from fragments vs smem w ------------------------
    float sum_wg = 0.0f;
#pragma unroll
    for (int mi = 0; mi < 2; mi++) {
        const int tt = wr * 32 + mi * 16 + g;
#pragma unroll
        for (int ni = 0; ni < 4; ni++) {
            const int ss = wc * 32 + ni * 8 + 2 * tg;
            const float* a = acc[mi][ni];
            float2 f0 = __half22float2(*(const __half2*)&smW[tt * WSTR + ss]);
            float2 f1 = __half22float2(*(const __half2*)&smW[(tt + 8) * WSTR + ss]);
            sum_wg += f0.x * a[0] + f0.y * a[1] + f1.x * a[2] + f1.y * a[3];
        }
    }

    // ---- reduce + accumulate --------------------------------------------------
#pragma unroll
    for (int o = 16; o > 0; o >>= 1) {
        sum_w  += __shfl_down_sync(0xFFFFFFFFu, sum_w,  o);
        sum_wg += __shfl_down_sync(0xFFFFFFFFu, sum_wg, o);
    }
    if (lane == 0) { red[warp] = sum_w; red[16 + warp] = sum_wg; }
    __syncthreads();
    if (tid == 0) {
        float W = 0.0f, WG = 0.0f;
#pragma unroll
        for (int i = 0; i < 16; i++) { W += red[i]; WG += red[16 + i]; }
        atomicAdd(&g_den[b], W);
        atomicAdd(&g_num[b], 2.0f * (W - WG));
    }
}

// ---------------------------------------------------------------------------
// Finalize: mean over batches of num / max(den, 1e-6)
// ---------------------------------------------------------------------------
__global__ void final_kernel(float* __restrict__ out) {
    int lane = threadIdx.x;
    float r = 0.0f;
    if (lane < BB) r = g_num[lane] / fmaxf(g_den[lane], 1e-6f);
#pragma unroll
    for (int o = 16; o > 0; o >>= 1) r += __shfl_down_sync(0xFFFFFFFFu, r, o);
    if (lane == 0) out[0] = r * (1.0f / BB);
}

extern "C" void kernel_launch(void* const* d_in, const int* in_sizes, int n_in,
                              void* d_out, int out_size) {
    const float* z  = (const float*)d_in[0];
    const float* dT = (const float*)d_in[1];
    if (n_in >= 2 && in_sizes[0] > in_sizes[1]) {
        const float* tmp = z; z = dT; dT = tmp;
    }
    (void)out_size;

    cudaFuncSetAttribute(fused_kernel,
                         cudaFuncAttributeMaxDynamicSharedMemorySize, SMEM_TOTAL);

    prep_kernel<<<512, 256>>>((const float4*)z);

    dim3 grid(TT / TILE, TT / TILE, BB);
    fused_kernel<<<grid, 512, SMEM_TOTAL>>>((const float4*)dT);

    final_kernel<<<1, 32>>>((float*)d_out);
}